// round 11
// baseline (speedup 1.0000x reference)
#include <cuda_runtime.h>

#define BB 4096
#define PP 128
#define GG 128

#define SCX (8000.0f / 79.0f)
#define SCY (8000.0f / 79.0f)
#define SCZ (2000.0f / 19.0f)
#define BX (-4000.0f)
#define BY (-4000.0f)
#define BZ (0.0f)

#define DIST_THRESH_SQ (500.0f * 500.0f)
#define BBOX_THRESH 0.1f
#define EOFF 2.0e8f              // keeps e strictly positive for all finite inputs
#define KEYMASK (~31)            // drop low 5 float bits, embed q (q < 32)

typedef unsigned long long ull;

// ---- packed f32x2 helpers (sm_103a) ----
__device__ __forceinline__ ull pack2(float lo, float hi) {
    ull r;
    asm("mov.b64 %0, {%1, %2};" : "=l"(r) : "f"(lo), "f"(hi));
    return r;
}
__device__ __forceinline__ void unpack2(ull v, float& lo, float& hi) {
    asm("mov.b64 {%0, %1}, %2;" : "=f"(lo), "=f"(hi) : "l"(v));
}
__device__ __forceinline__ ull fma2(ull a, ull b, ull c) {
    ull r;
    asm("fma.rn.f32x2 %0, %1, %2, %3;" : "=l"(r) : "l"(a), "l"(b), "l"(c));
    return r;
}
// (bits(s) & KEYMASK) | q in a single LOP3
__device__ __forceinline__ int keyfuse(float s, int q) {
    int r;
    asm("lop3.b32 %0, %1, %2, %3, 0xea;"   // (a & b) | c
        : "=r"(r) : "r"(__float_as_int(s)), "n"(KEYMASK), "r"(q));
    return r;
}

__global__ __launch_bounds__(PP, 9)
void proposal_layer_kernel(const int*   __restrict__ topk_index,      // [B,P,3]
                           const float* __restrict__ topk_confs,      // [B,P]
                           const float* __restrict__ match_bbox_preds,// [B,P,2]
                           const float* __restrict__ roots_3d,        // [B,G,3]
                           const float* __restrict__ gt_bbox,         // [B,G,2]
                           const int*   __restrict__ num_person,      // [B]
                           float*       __restrict__ out)             // [B,P,7]
{
    const int b = blockIdx.x;
    const int t = threadIdx.x;  // 0..127, one proposal per thread

    __shared__ __align__(16) float s_nx[GG];   // -rx
    __shared__ __align__(16) float s_ny[GG];   // -ry
    __shared__ __align__(16) float s_nz[GG];   // -rz
    __shared__ __align__(16) float s_h [GG];   // |r|^2/2 + EOFF, +INF for g >= n
    __shared__ float2 s_bbox[GG];
    // 224 float4: first used as raw staging (roots 96 + tidx 96), later as s_out
    __shared__ __align__(16) float4 s_buf[224];

    const int n = num_person[b];  // uniform, broadcast

    // ---- phase 1: fully-coalesced vectorized staging (LDG.128 only) ----
    {
        const float4* groots = (const float4*)(roots_3d + (size_t)b * (GG * 3));
        const float4* gtidx  = (const float4*)(topk_index + (size_t)b * (PP * 3));
        if (t < 96) {
            s_buf[t]      = groots[t];   // 384 floats of roots
            s_buf[96 + t] = gtidx[t];    // 384 ints of topk_index (bit-copied)
        }
        // gt_bbox per-thread: stride 8B -> coalesced LDG.64
        const float* gb = gt_bbox + ((size_t)b * GG + t) * 2;
        s_bbox[t] = make_float2(gb[0], gb[1]);
    }
    __syncthreads();

    // ---- phase 2: convert raw -> SoA (stride-3 LDS, conflict-free) ----
    {
        const float* rr = (const float*)s_buf;
        float rx = rr[3 * t], ry = rr[3 * t + 1], rz = rr[3 * t + 2];
        s_nx[t] = -rx;
        s_ny[t] = -ry;
        s_nz[t] = -rz;
        float hv = __fmaf_rn(0.5f, __fmaf_rn(rz, rz, __fmaf_rn(ry, ry, rx * rx)), EOFF);
        s_h[t]  = (t < n) ? hv : __int_as_float(0x7F800000);
    }
    const int* it = (const int*)(s_buf + 96);
    const float cx = (float)it[3 * t]     * SCX + BX;
    const float cy = (float)it[3 * t + 1] * SCY + BY;
    const float cz = (float)it[3 * t + 2] * SCZ + BZ;

    // remaining per-proposal inputs (coalesced LDG.32 / LDG.64)
    const float conf = topk_confs[(size_t)b * PP + t];
    const float* mp = match_bbox_preds + ((size_t)b * PP + t) * 2;
    const float pb0 = mp[0];
    const float pb1 = mp[1];
    __syncthreads();   // SoA ready; raw staging fully consumed (s_buf reusable)

    // ---- phase 3: scan, 4 int-key chains over INF-padded chunks ----
    const ull cxx = pack2(cx, cx);
    const ull cyy = pack2(cy, cy);
    const ull czz = pack2(cz, cz);

    const ulonglong2* px = (const ulonglong2*)s_nx;
    const ulonglong2* py = (const ulonglong2*)s_ny;
    const ulonglong2* pz = (const ulonglong2*)s_nz;
    const ulonglong2* ph = (const ulonglong2*)s_h;

    int bk0 = 0x7FFFFFFF, bk1 = 0x7FFFFFFF, bk2 = 0x7FFFFFFF, bk3 = 0x7FFFFFFF;
    const int nbc = (n + 3) >> 2;   // ceil(n/4); pads are +INF, never win
    #pragma unroll 4
    for (int q = 0; q < nbc; ++q) {
        ulonglong2 X = px[q];   // LDS.128 broadcast
        ulonglong2 Y = py[q];
        ulonglong2 Z = pz[q];
        ulonglong2 H = ph[q];

        ull eA = fma2(cxx, X.x, fma2(cyy, Y.x, fma2(czz, Z.x, H.x)));
        ull eB = fma2(cxx, X.y, fma2(cyy, Y.y, fma2(czz, Z.y, H.y)));
        float s0, s1, s2, s3;
        unpack2(eA, s0, s1);
        unpack2(eB, s2, s3);

        bk0 = min(bk0, keyfuse(s0, q));   // LOP3 + IMNMX
        bk1 = min(bk1, keyfuse(s1, q));
        bk2 = min(bk2, keyfuse(s2, q));
        bk3 = min(bk3, keyfuse(s3, q));
    }

    // merge chains (masked value, strict <; residue order = g order)
    int best_mv = bk0 & KEYMASK;
    int bi = ((bk0 & 31) << 2);
    { int mv = bk1 & KEYMASK; if (mv < best_mv) { best_mv = mv; bi = ((bk1 & 31) << 2) + 1; } }
    { int mv = bk2 & KEYMASK; if (mv < best_mv) { best_mv = mv; bi = ((bk2 & 31) << 2) + 2; } }
    { int mv = bk3 & KEYMASK; if (mv < best_mv) { best_mv = mv; bi = ((bk3 & 31) << 2) + 3; } }

    // ---- exact fp32 threshold recheck for chosen bi ----
    // d2 <= 500^2  <=>  e+EOFF <= 0.5*(500^2 - cc) + EOFF
    const float cc = __fmaf_rn(cz, cz, __fmaf_rn(cy, cy, cx * cx));
    const float e_best = __fmaf_rn(cx, s_nx[bi],
                        __fmaf_rn(cy, s_ny[bi],
                        __fmaf_rn(cz, s_nz[bi], s_h[bi])));
    const float thresh_e = __fmaf_rn(-0.5f, cc, 0.5f * DIST_THRESH_SQ + EOFF);
    const bool matched = !(e_best > thresh_e);
    const float p2g = matched ? (float)bi : -1.0f;

    float2 mb = s_bbox[bi];
    bool ow = matched && ((pb0 < mb.x - BBOX_THRESH) || (pb1 < mb.y - BBOX_THRESH));
    const float o5 = ow ? mb.x : pb0;
    const float o6 = ow ? mb.y : pb1;

    // ---- phase 4: stage [P,7] tile in s_buf (stride 7 -> conflict-free) ----
    float* so = (float*)s_buf + t * 7;
    so[0] = cx; so[1] = cy; so[2] = cz;
    so[3] = p2g; so[4] = conf;
    so[5] = o5;  so[6] = o6;
    __syncthreads();

    // coalesced float4 store of 896 floats
    float4* dst = (float4*)(out + (size_t)b * (PP * 7));
    #pragma unroll
    for (int i = t; i < 224; i += PP)
        dst[i] = s_buf[i];
}

extern "C" void kernel_launch(void* const* d_in, const int* in_sizes, int n_in,
                              void* d_out, int out_size)
{
    const int*   topk_index       = (const int*)  d_in[0];
    const float* topk_confs       = (const float*)d_in[1];
    const float* match_bbox_preds = (const float*)d_in[2];
    const float* roots_3d         = (const float*)d_in[3];
    const float* gt_bbox          = (const float*)d_in[4];
    const int*   num_person       = (const int*)  d_in[5];
    float* out = (float*)d_out;

    proposal_layer_kernel<<<BB, PP>>>(topk_index, topk_confs, match_bbox_preds,
                                      roots_3d, gt_bbox, num_person, out);
}

// round 12
// speedup vs baseline: 1.0017x; 1.0017x over previous
#include <cuda_runtime.h>

#define BB 4096
#define PP 128
#define GG 128
#define GRID (BB / 2)            // 2048 CTAs, each handles batches b and b+GRID

#define SCX (8000.0f / 79.0f)
#define SCY (8000.0f / 79.0f)
#define SCZ (2000.0f / 19.0f)
#define BX (-4000.0f)
#define BY (-4000.0f)
#define BZ (0.0f)

#define DIST_THRESH_SQ (500.0f * 500.0f)
#define BBOX_THRESH 0.1f
#define EOFF 2.0e8f              // keeps e strictly positive for all finite inputs
#define KEYMASK (~31)            // drop low 5 float bits, embed q (q < 32)

typedef unsigned long long ull;

// ---- packed f32x2 helpers (sm_103a) ----
__device__ __forceinline__ ull pack2(float lo, float hi) {
    ull r;
    asm("mov.b64 %0, {%1, %2};" : "=l"(r) : "f"(lo), "f"(hi));
    return r;
}
__device__ __forceinline__ void unpack2(ull v, float& lo, float& hi) {
    asm("mov.b64 {%0, %1}, %2;" : "=f"(lo), "=f"(hi) : "l"(v));
}
__device__ __forceinline__ ull fma2(ull a, ull b, ull c) {
    ull r;
    asm("fma.rn.f32x2 %0, %1, %2, %3;" : "=l"(r) : "l"(a), "l"(b), "l"(c));
    return r;
}
// (bits(s) & KEYMASK) | q in a single LOP3
__device__ __forceinline__ int keyfuse(float s, int q) {
    int r;
    asm("lop3.b32 %0, %1, %2, %3, 0xea;"   // (a & b) | c
        : "=r"(r) : "r"(__float_as_int(s)), "n"(KEYMASK), "r"(q));
    return r;
}

// ---- cp.async helpers ----
__device__ __forceinline__ void cpa16(void* s, const void* g) {
    unsigned sa = (unsigned)__cvta_generic_to_shared(s);
    asm volatile("cp.async.ca.shared.global [%0], [%1], 16;" :: "r"(sa), "l"(g));
}
__device__ __forceinline__ void cpa4(void* s, const void* g) {
    unsigned sa = (unsigned)__cvta_generic_to_shared(s);
    asm volatile("cp.async.ca.shared.global [%0], [%1], 4;" :: "r"(sa), "l"(g));
}

struct __align__(16) RawBuf {     // 5648 B
    float roots[GG * 3];
    float bbox [GG * 2];
    int   tidx [PP * 3];
    float conf [PP];
    float match[PP * 2];
    int   np;
    int   pad[3];
};

__global__ __launch_bounds__(PP, 12)
void proposal_layer_kernel(const int*   __restrict__ topk_index,      // [B,P,3]
                           const float* __restrict__ topk_confs,      // [B,P]
                           const float* __restrict__ match_bbox_preds,// [B,P,2]
                           const float* __restrict__ roots_3d,        // [B,G,3]
                           const float* __restrict__ gt_bbox,         // [B,G,2]
                           const int*   __restrict__ num_person,      // [B]
                           float*       __restrict__ out)             // [B,P,7]
{
    const int t  = threadIdx.x;           // 0..127
    const int b1 = blockIdx.x;
    const int b2 = blockIdx.x + GRID;

    __shared__ RawBuf raw;                               // batch 2 raw staging
    __shared__ __align__(16) float s_nx[GG];
    __shared__ __align__(16) float s_ny[GG];
    __shared__ __align__(16) float s_nz[GG];
    __shared__ __align__(16) float s_h [GG];
    __shared__ float2 s_bbox[GG];
    __shared__ __align__(16) float4 s_out4[224];         // [P,7] output staging

    // ---- fire-and-forget prefetch of batch 2 (hidden behind batch-1 work) ----
    if (t < 96) cpa16(&raw.roots[t * 4], roots_3d         + (size_t)b2 * (GG * 3) + t * 4);
    if (t < 64) cpa16(&raw.bbox [t * 4], gt_bbox          + (size_t)b2 * (GG * 2) + t * 4);
    if (t < 96) cpa16(&raw.tidx [t * 4], topk_index       + (size_t)b2 * (PP * 3) + t * 4);
    if (t < 32) cpa16(&raw.conf [t * 4], topk_confs       + (size_t)b2 * PP       + t * 4);
    if (t < 64) cpa16(&raw.match[t * 4], match_bbox_preds + (size_t)b2 * (PP * 2) + t * 4);
    if (t == 0) cpa4 (&raw.np, num_person + b2);
    asm volatile("cp.async.commit_group;" ::: "memory");

    // scan + finalize + output for one batch (SoA/bbox/per-prop regs already set)
    auto process = [&](int b, int n, float cx, float cy, float cz,
                       float conf, float pb0, float pb1) {
        const ull cxx = pack2(cx, cx);
        const ull cyy = pack2(cy, cy);
        const ull czz = pack2(cz, cz);

        const ulonglong2* px = (const ulonglong2*)s_nx;
        const ulonglong2* py = (const ulonglong2*)s_ny;
        const ulonglong2* pz = (const ulonglong2*)s_nz;
        const ulonglong2* ph = (const ulonglong2*)s_h;

        int bk0 = 0x7FFFFFFF, bk1 = 0x7FFFFFFF, bk2 = 0x7FFFFFFF, bk3 = 0x7FFFFFFF;
        const int nbc = (n + 3) >> 2;   // INF pads never win
        #pragma unroll 2
        for (int q = 0; q < nbc; ++q) {
            ulonglong2 X = px[q];
            ulonglong2 Y = py[q];
            ulonglong2 Z = pz[q];
            ulonglong2 H = ph[q];

            ull eA = fma2(cxx, X.x, fma2(cyy, Y.x, fma2(czz, Z.x, H.x)));
            ull eB = fma2(cxx, X.y, fma2(cyy, Y.y, fma2(czz, Z.y, H.y)));
            float s0, s1, s2, s3;
            unpack2(eA, s0, s1);
            unpack2(eB, s2, s3);

            bk0 = min(bk0, keyfuse(s0, q));
            bk1 = min(bk1, keyfuse(s1, q));
            bk2 = min(bk2, keyfuse(s2, q));
            bk3 = min(bk3, keyfuse(s3, q));
        }

        // merge chains (masked value, strict <; residue order = g order)
        int best_mv = bk0 & KEYMASK;
        int bi = ((bk0 & 31) << 2);
        { int mv = bk1 & KEYMASK; if (mv < best_mv) { best_mv = mv; bi = ((bk1 & 31) << 2) + 1; } }
        { int mv = bk2 & KEYMASK; if (mv < best_mv) { best_mv = mv; bi = ((bk2 & 31) << 2) + 2; } }
        { int mv = bk3 & KEYMASK; if (mv < best_mv) { best_mv = mv; bi = ((bk3 & 31) << 2) + 3; } }

        // exact fp32 threshold recheck: d2<=500^2 <=> e+EOFF <= 0.5*(500^2-cc)+EOFF
        const float cc = __fmaf_rn(cz, cz, __fmaf_rn(cy, cy, cx * cx));
        const float e_best = __fmaf_rn(cx, s_nx[bi],
                            __fmaf_rn(cy, s_ny[bi],
                            __fmaf_rn(cz, s_nz[bi], s_h[bi])));
        const float thresh_e = __fmaf_rn(-0.5f, cc, 0.5f * DIST_THRESH_SQ + EOFF);
        const bool matched = !(e_best > thresh_e);
        const float p2g = matched ? (float)bi : -1.0f;

        float2 mb = s_bbox[bi];
        bool ow = matched && ((pb0 < mb.x - BBOX_THRESH) || (pb1 < mb.y - BBOX_THRESH));
        const float o5 = ow ? mb.x : pb0;
        const float o6 = ow ? mb.y : pb1;

        float* so = (float*)s_out4 + t * 7;   // stride 7 -> conflict-free
        so[0] = cx; so[1] = cy; so[2] = cz;
        so[3] = p2g; so[4] = conf;
        so[5] = o5;  so[6] = o6;
        __syncthreads();

        float4* dst = (float4*)(out + (size_t)b * (PP * 7));
        #pragma unroll
        for (int i = t; i < 224; i += PP)
            dst[i] = s_out4[i];
    };

    // ================= batch 1: direct staging (champion R8 pattern) =========
    const int n1 = num_person[b1];
    {
        const float* r = roots_3d + ((size_t)b1 * GG + t) * 3;
        float rx = r[0], ry = r[1], rz = r[2];
        s_nx[t] = -rx;
        s_ny[t] = -ry;
        s_nz[t] = -rz;
        float hv = __fmaf_rn(0.5f, __fmaf_rn(rz, rz, __fmaf_rn(ry, ry, rx * rx)), EOFF);
        s_h[t]  = (t < n1) ? hv : __int_as_float(0x7F800000);
        const float* gb = gt_bbox + ((size_t)b1 * GG + t) * 2;
        s_bbox[t] = make_float2(gb[0], gb[1]);
    }
    __syncthreads();

    {
        const int* ti = topk_index + ((size_t)b1 * PP + t) * 3;
        const float cx = (float)ti[0] * SCX + BX;
        const float cy = (float)ti[1] * SCY + BY;
        const float cz = (float)ti[2] * SCZ + BZ;
        const float conf = topk_confs[(size_t)b1 * PP + t];
        const float* mp = match_bbox_preds + ((size_t)b1 * PP + t) * 2;
        process(b1, n1, cx, cy, cz, conf, mp[0], mp[1]);
    }

    // ================= batch 2: zero-LDG, from prefetched smem ===============
    asm volatile("cp.async.wait_group 0;" ::: "memory");
    __syncthreads();   // everyone done with batch-1 SoA/s_out; raw visible

    const int n2 = raw.np;
    {
        float rx = raw.roots[3 * t], ry = raw.roots[3 * t + 1], rz = raw.roots[3 * t + 2];
        s_nx[t] = -rx;
        s_ny[t] = -ry;
        s_nz[t] = -rz;
        float hv = __fmaf_rn(0.5f, __fmaf_rn(rz, rz, __fmaf_rn(ry, ry, rx * rx)), EOFF);
        s_h[t]  = (t < n2) ? hv : __int_as_float(0x7F800000);
        s_bbox[t] = make_float2(raw.bbox[2 * t], raw.bbox[2 * t + 1]);
    }
    const float cx2 = (float)raw.tidx[3 * t]     * SCX + BX;
    const float cy2 = (float)raw.tidx[3 * t + 1] * SCY + BY;
    const float cz2 = (float)raw.tidx[3 * t + 2] * SCZ + BZ;
    const float conf2 = raw.conf[t];
    const float pb0_2 = raw.match[2 * t];
    const float pb1_2 = raw.match[2 * t + 1];
    __syncthreads();

    process(b2, n2, cx2, cy2, cz2, conf2, pb0_2, pb1_2);
}

extern "C" void kernel_launch(void* const* d_in, const int* in_sizes, int n_in,
                              void* d_out, int out_size)
{
    const int*   topk_index       = (const int*)  d_in[0];
    const float* topk_confs       = (const float*)d_in[1];
    const float* match_bbox_preds = (const float*)d_in[2];
    const float* roots_3d         = (const float*)d_in[3];
    const float* gt_bbox          = (const float*)d_in[4];
    const int*   num_person       = (const int*)  d_in[5];
    float* out = (float*)d_out;

    proposal_layer_kernel<<<GRID, PP>>>(topk_index, topk_confs, match_bbox_preds,
                                        roots_3d, gt_bbox, num_person, out);
}